// round 1
// baseline (speedup 1.0000x reference)
#include <cuda_runtime.h>
#include <math.h>

// Problem constants (fixed by the dataset)
#define Bc   4
#define Nc   50000
#define Ec   800000
#define INc  128
#define Hc   4
#define Dc   32
#define HDc  128
#define BNc  (Bc * Nc)          // 200000 rows
#define GAT_SLOPE 0.2f
#define ACT_SLOPE 0.01f
#define BN_EPS    1e-5f

// ---------------- scratch (device globals; no allocation allowed) ----------
__device__ float    g_feat[(size_t)BNc * HDc];   // 102.4 MB
__device__ float    g_el[BNc * Hc];
__device__ float    g_er[BNc * Hc];
__device__ unsigned g_mkey[BNc * Hc];            // ordered-uint encoded segment max
__device__ float    g_den[BNc * Hc];             // softmax denominator
__device__ float    g_sum[HDc];
__device__ float    g_sq[HDc];
__device__ float    g_scale[HDc];
__device__ float    g_shift[HDc];

// monotone float<->uint encoding so atomicMax(unsigned) == float max
__device__ __forceinline__ unsigned enc_f(float f) {
    unsigned u = __float_as_uint(f);
    return (u & 0x80000000u) ? ~u : (u | 0x80000000u);
}
__device__ __forceinline__ float dec_f(unsigned k) {
    return __uint_as_float((k & 0x80000000u) ? (k ^ 0x80000000u) : ~k);
}

__device__ __forceinline__ float leaky(float v, float s) {
    return v >= 0.0f ? v : s * v;
}

// ---------------- 0: zero-init all accumulators + output --------------------
__global__ void k_init(float4* out) {
    int i = blockIdx.x * blockDim.x + threadIdx.x;
    int stride = gridDim.x * blockDim.x;
    const int n4 = BNc * HDc / 4;
    float4 z = make_float4(0.f, 0.f, 0.f, 0.f);
    for (int p = i; p < n4; p += stride) out[p] = z;
    for (int p = i; p < BNc * Hc; p += stride) { g_mkey[p] = 0u; g_den[p] = 0.f; }
    if (i < HDc) { g_sum[i] = 0.f; g_sq[i] = 0.f; }
}

// ---------------- 1: feat = x @ W  (200000 x 128 @ 128 x 128) --------------
// Block: 256 threads, 32 rows x 128 cols, each thread 4 rows x 4 cols.
__global__ void k_gemm(const float* __restrict__ x, const float* __restrict__ W) {
    __shared__ float Ws[64][128];   // 32 KB
    __shared__ float xs[32][64];    //  8 KB
    const int t = threadIdx.x;
    const int row0 = blockIdx.x * 32;
    const int jg = t & 31;   // column group (4 cols)
    const int rg = t >> 5;   // row group (4 rows), 0..7

    float4 acc0 = make_float4(0, 0, 0, 0);
    float4 acc1 = make_float4(0, 0, 0, 0);
    float4 acc2 = make_float4(0, 0, 0, 0);
    float4 acc3 = make_float4(0, 0, 0, 0);

    for (int kc = 0; kc < 128; kc += 64) {
        // W rows kc..kc+63 are contiguous: flat float4 copy (8192 floats)
        const float4* wsrc = (const float4*)(W + kc * 128);
        float4* wdst = (float4*)&Ws[0][0];
#pragma unroll
        for (int i = 0; i < 8; i++) wdst[i * 256 + t] = wsrc[i * 256 + t];
        // x tile: 32 rows x 64 cols
#pragma unroll
        for (int i = 0; i < 2; i++) {
            int idx = i * 256 + t;       // float4 index, 16 per row
            int r = idx >> 4;
            int c4 = idx & 15;
            ((float4*)&xs[r][0])[c4] =
                *(const float4*)(x + (size_t)(row0 + r) * 128 + kc + c4 * 4);
        }
        __syncthreads();
#pragma unroll 8
        for (int k = 0; k < 64; k++) {
            float4 w4 = *(const float4*)&Ws[k][jg * 4];
            float x0 = xs[rg * 4 + 0][k];
            float x1 = xs[rg * 4 + 1][k];
            float x2 = xs[rg * 4 + 2][k];
            float x3 = xs[rg * 4 + 3][k];
            acc0.x += x0 * w4.x; acc0.y += x0 * w4.y; acc0.z += x0 * w4.z; acc0.w += x0 * w4.w;
            acc1.x += x1 * w4.x; acc1.y += x1 * w4.y; acc1.z += x1 * w4.z; acc1.w += x1 * w4.w;
            acc2.x += x2 * w4.x; acc2.y += x2 * w4.y; acc2.z += x2 * w4.z; acc2.w += x2 * w4.w;
            acc3.x += x3 * w4.x; acc3.y += x3 * w4.y; acc3.z += x3 * w4.z; acc3.w += x3 * w4.w;
        }
        __syncthreads();
    }
    float* base = g_feat + (size_t)(row0 + rg * 4) * 128 + jg * 4;
    *(float4*)(base + 0 * 128) = acc0;
    *(float4*)(base + 1 * 128) = acc1;
    *(float4*)(base + 2 * 128) = acc2;
    *(float4*)(base + 3 * 128) = acc3;
}

// ---------------- 2: el/er = einsum(feat, attn_l/r) ------------------------
// one warp per row; lane owns 4 consecutive channels; 8 lanes per head
__global__ void k_eler(const float* __restrict__ attn_l,
                       const float* __restrict__ attn_r) {
    int gw = (blockIdx.x * blockDim.x + threadIdx.x) >> 5;
    int lane = threadIdx.x & 31;
    if (gw >= BNc) return;
    float4 f  = *(const float4*)(g_feat + (size_t)gw * 128 + lane * 4);
    float4 al = *(const float4*)(attn_l + lane * 4);
    float4 ar = *(const float4*)(attn_r + lane * 4);
    float sl = f.x * al.x + f.y * al.y + f.z * al.z + f.w * al.w;
    float sr = f.x * ar.x + f.y * ar.y + f.z * ar.z + f.w * ar.w;
#pragma unroll
    for (int o = 4; o > 0; o >>= 1) {
        sl += __shfl_down_sync(0xffffffffu, sl, o);
        sr += __shfl_down_sync(0xffffffffu, sr, o);
    }
    if ((lane & 7) == 0) {
        int h = lane >> 3;
        g_el[gw * 4 + h] = sl;
        g_er[gw * 4 + h] = sr;
    }
}

// ---------------- 3: segment max of e over dst ------------------------------
__global__ void k_edge_max(const int* __restrict__ src, const int* __restrict__ dst, int E) {
    int e = blockIdx.x * blockDim.x + threadIdx.x;
    if (e >= E) return;
    int b = blockIdx.y;
    int s = src[e], d = dst[e];
    size_t is = ((size_t)b * Nc + s) * 4;
    size_t id = ((size_t)b * Nc + d) * 4;
    float4 el4 = *(const float4*)(g_el + is);
    float4 er4 = *(const float4*)(g_er + id);
    unsigned* mk = g_mkey + id;
    atomicMax(&mk[0], enc_f(leaky(el4.x + er4.x, GAT_SLOPE)));
    atomicMax(&mk[1], enc_f(leaky(el4.y + er4.y, GAT_SLOPE)));
    atomicMax(&mk[2], enc_f(leaky(el4.z + er4.z, GAT_SLOPE)));
    atomicMax(&mk[3], enc_f(leaky(el4.w + er4.w, GAT_SLOPE)));
}

// ---------------- 4: segment sum of exp(e - m) over dst ---------------------
__global__ void k_edge_sum(const int* __restrict__ src, const int* __restrict__ dst, int E) {
    int e = blockIdx.x * blockDim.x + threadIdx.x;
    if (e >= E) return;
    int b = blockIdx.y;
    int s = src[e], d = dst[e];
    size_t is = ((size_t)b * Nc + s) * 4;
    size_t id = ((size_t)b * Nc + d) * 4;
    float4 el4 = *(const float4*)(g_el + is);
    float4 er4 = *(const float4*)(g_er + id);
    uint4 mk = *(const uint4*)(g_mkey + id);
    float4 w;
    w.x = expf(leaky(el4.x + er4.x, GAT_SLOPE) - dec_f(mk.x));
    w.y = expf(leaky(el4.y + er4.y, GAT_SLOPE) - dec_f(mk.y));
    w.z = expf(leaky(el4.z + er4.z, GAT_SLOPE) - dec_f(mk.z));
    w.w = expf(leaky(el4.w + er4.w, GAT_SLOPE) - dec_f(mk.w));
    atomicAdd((float4*)(g_den + id), w);   // sm_90+ vector atomic
}

// ---------------- 5: weighted scatter aggregation ---------------------------
// one warp per (b, edge); lane covers 4 consecutive channels; h = lane>>3
__global__ void k_edge_agg(const int* __restrict__ src, const int* __restrict__ dst,
                           float* __restrict__ out, int E) {
    int gw = (blockIdx.x * blockDim.x + threadIdx.x) >> 5;
    int lane = threadIdx.x & 31;
    if (gw >= E) return;
    int b = blockIdx.y;
    int s = src[gw], d = dst[gw];
    size_t is = (size_t)b * Nc + s;
    size_t id = (size_t)b * Nc + d;
    int h = lane >> 3;
    float el_ = g_el[is * 4 + h];
    float er_ = g_er[id * 4 + h];
    float m_  = dec_f(g_mkey[id * 4 + h]);
    float dn_ = g_den[id * 4 + h];
    float ev = leaky(el_ + er_, GAT_SLOPE);
    float alpha = expf(ev - m_) / fmaxf(dn_, 1e-9f);
    float4 f = *(const float4*)(g_feat + is * 128 + lane * 4);
    f.x *= alpha; f.y *= alpha; f.z *= alpha; f.w *= alpha;
    atomicAdd((float4*)(out + id * 128 + lane * 4), f);
}

// ---------------- 6: BN statistics ------------------------------------------
__global__ void k_bnstats(const float* __restrict__ out) {
    int c = threadIdx.x & 127;
    int r = blockIdx.x * 2 + (threadIdx.x >> 7);
    float s = 0.f, q = 0.f;
    for (; r < BNc; r += gridDim.x * 2) {
        float v = out[(size_t)r * 128 + c];
        s += v; q += v * v;
    }
    atomicAdd(&g_sum[c], s);
    atomicAdd(&g_sq[c], q);
}

__global__ void k_bnfinal(const float* __restrict__ gamma, const float* __restrict__ beta) {
    int c = threadIdx.x;
    float mean = g_sum[c] / (float)BNc;
    float var  = g_sq[c] / (float)BNc - mean * mean;
    float sc = gamma[c] * rsqrtf(var + BN_EPS);
    g_scale[c] = sc;
    g_shift[c] = beta[c] - mean * sc;
}

// ---------------- 7: BN apply + LeakyReLU (in place) -------------------------
__global__ void k_bnapply(float4* out) {
    int i = blockIdx.x * blockDim.x + threadIdx.x;
    int stride = gridDim.x * blockDim.x;
    const int n4 = BNc * HDc / 4;
    for (int p = i; p < n4; p += stride) {
        float4 v = out[p];
        int c = (p & 31) * 4;  // 32 float4 per 128-channel row
        v.x = leaky(v.x * g_scale[c + 0] + g_shift[c + 0], ACT_SLOPE);
        v.y = leaky(v.y * g_scale[c + 1] + g_shift[c + 1], ACT_SLOPE);
        v.z = leaky(v.z * g_scale[c + 2] + g_shift[c + 2], ACT_SLOPE);
        v.w = leaky(v.w * g_scale[c + 3] + g_shift[c + 3], ACT_SLOPE);
        out[p] = v;
    }
}

// ---------------- launch -----------------------------------------------------
extern "C" void kernel_launch(void* const* d_in, const int* in_sizes, int n_in,
                              void* d_out, int out_size) {
    const float* xx     = (const float*)d_in[0];
    const float* W      = (const float*)d_in[1];
    const float* attn_l = (const float*)d_in[2];
    const float* attn_r = (const float*)d_in[3];
    const float* gamma  = (const float*)d_in[4];
    const float* beta   = (const float*)d_in[5];
    const int*   src    = (const int*)d_in[6];
    const int*   dst    = (const int*)d_in[7];
    float* out = (float*)d_out;
    const int E = in_sizes[6];

    k_init<<<1184, 256>>>((float4*)out);
    k_gemm<<<BNc / 32, 256>>>(xx, W);
    k_eler<<<(BNc * 32 + 255) / 256, 256>>>(attn_l, attn_r);

    dim3 gmax((E + 255) / 256, Bc);
    k_edge_max<<<gmax, 256>>>(src, dst, E);
    k_edge_sum<<<gmax, 256>>>(src, dst, E);

    dim3 gagg(((size_t)E * 32 + 255) / 256, Bc);
    k_edge_agg<<<gagg, 256>>>(src, dst, out, E);

    k_bnstats<<<512, 256>>>(out);
    k_bnfinal<<<1, 128>>>(gamma, beta);
    k_bnapply<<<2048, 256>>>((float4*)out);
}

// round 2
// speedup vs baseline: 1.1591x; 1.1591x over previous
#include <cuda_runtime.h>
#include <math.h>

// Problem constants (fixed by the dataset)
#define Bc   4
#define Nc   50000
#define EcMax 800000
#define INc  128
#define Hc   4
#define Dc   32
#define HDc  128
#define BNc  (Bc * Nc)          // 200000 rows
#define GAT_SLOPE 0.2f
#define ACT_SLOPE 0.01f
#define BN_EPS    1e-5f

// ---------------- scratch (device globals; no allocation allowed) ----------
__device__ float    g_feat[(size_t)BNc * HDc];   // 102.4 MB
__device__ float4   g_el[BNc];                   // per-node, per-head (4 heads)
__device__ float4   g_er[BNc];
__device__ int      g_cnt[Nc];                   // in-degree histogram
__device__ int      g_off[Nc + 1];               // CSR offsets
__device__ int      g_wr[Nc];                    // scatter write cursors
__device__ int      g_csrc[EcMax];               // CSR: src node per slot
__device__ float    g_sum[HDc];
__device__ float    g_sq[HDc];
__device__ float    g_scale[HDc];
__device__ float    g_shift[HDc];

__device__ __forceinline__ float leaky(float v, float s) {
    return v >= 0.0f ? v : s * v;
}

// ---------------- 0: zero-init histogram + BN accumulators ------------------
__global__ void k_init() {
    int i = blockIdx.x * blockDim.x + threadIdx.x;
    int stride = gridDim.x * blockDim.x;
    for (int p = i; p < Nc; p += stride) g_cnt[p] = 0;
    if (i < HDc) { g_sum[i] = 0.f; g_sq[i] = 0.f; }
}

// ---------------- CSR build --------------------------------------------------
__global__ void k_hist(const int* __restrict__ dst, int E) {
    int e = blockIdx.x * blockDim.x + threadIdx.x;
    if (e < E) atomicAdd(&g_cnt[dst[e]], 1);
}

// single block, 1024 threads: exclusive scan of g_cnt -> g_off, copy to g_wr
__global__ void k_scan() {
    __shared__ int ssum[1024];
    const int t = threadIdx.x;
    const int per = (Nc + 1023) / 1024;   // 49
    const int base = t * per;
    int s = 0;
    for (int i = 0; i < per; i++) {
        int idx = base + i;
        if (idx < Nc) s += g_cnt[idx];
    }
    ssum[t] = s;
    __syncthreads();
    // Hillis-Steele inclusive scan over 1024 partials
    for (int o = 1; o < 1024; o <<= 1) {
        int v = (t >= o) ? ssum[t - o] : 0;
        __syncthreads();
        ssum[t] += v;
        __syncthreads();
    }
    int run = ssum[t] - s;  // exclusive prefix for this thread's segment
    for (int i = 0; i < per; i++) {
        int idx = base + i;
        if (idx < Nc) {
            g_off[idx] = run;
            g_wr[idx]  = run;
            run += g_cnt[idx];
        }
    }
    if (t == 1023) g_off[Nc] = ssum[1023];
}

__global__ void k_scatter(const int* __restrict__ src, const int* __restrict__ dst, int E) {
    int e = blockIdx.x * blockDim.x + threadIdx.x;
    if (e < E) {
        int pos = atomicAdd(&g_wr[dst[e]], 1);
        g_csrc[pos] = src[e];
    }
}

// ---------------- 1: feat = x @ W, fused el/er epilogue --------------------
// Block: 256 threads, 32 rows x 128 cols, each thread 4 rows x 4 cols.
__global__ void k_gemm(const float* __restrict__ x, const float* __restrict__ W,
                       const float* __restrict__ attn_l, const float* __restrict__ attn_r) {
    __shared__ float Ws[64][128];   // 32 KB
    __shared__ float xs[32][64];    //  8 KB
    __shared__ float sEl[32][4];
    __shared__ float sEr[32][4];
    const int t = threadIdx.x;
    const int row0 = blockIdx.x * 32;
    const int jg = t & 31;   // column group (4 cols)
    const int rg = t >> 5;   // row group (4 rows), 0..7

    if (t < 128) { ((float*)sEl)[t] = 0.f; ((float*)sEr)[t] = 0.f; }

    float4 acc0 = make_float4(0, 0, 0, 0);
    float4 acc1 = make_float4(0, 0, 0, 0);
    float4 acc2 = make_float4(0, 0, 0, 0);
    float4 acc3 = make_float4(0, 0, 0, 0);

    for (int kc = 0; kc < 128; kc += 64) {
        const float4* wsrc = (const float4*)(W + kc * 128);
        float4* wdst = (float4*)&Ws[0][0];
#pragma unroll
        for (int i = 0; i < 8; i++) wdst[i * 256 + t] = wsrc[i * 256 + t];
#pragma unroll
        for (int i = 0; i < 2; i++) {
            int idx = i * 256 + t;       // float4 index, 16 per row
            int r = idx >> 4;
            int c4 = idx & 15;
            ((float4*)&xs[r][0])[c4] =
                *(const float4*)(x + (size_t)(row0 + r) * 128 + kc + c4 * 4);
        }
        __syncthreads();
#pragma unroll 8
        for (int k = 0; k < 64; k++) {
            float4 w4 = *(const float4*)&Ws[k][jg * 4];
            float x0 = xs[rg * 4 + 0][k];
            float x1 = xs[rg * 4 + 1][k];
            float x2 = xs[rg * 4 + 2][k];
            float x3 = xs[rg * 4 + 3][k];
            acc0.x += x0 * w4.x; acc0.y += x0 * w4.y; acc0.z += x0 * w4.z; acc0.w += x0 * w4.w;
            acc1.x += x1 * w4.x; acc1.y += x1 * w4.y; acc1.z += x1 * w4.z; acc1.w += x1 * w4.w;
            acc2.x += x2 * w4.x; acc2.y += x2 * w4.y; acc2.z += x2 * w4.z; acc2.w += x2 * w4.w;
            acc3.x += x3 * w4.x; acc3.y += x3 * w4.y; acc3.z += x3 * w4.z; acc3.w += x3 * w4.w;
        }
        __syncthreads();
    }
    float* base = g_feat + (size_t)(row0 + rg * 4) * 128 + jg * 4;
    *(float4*)(base + 0 * 128) = acc0;
    *(float4*)(base + 1 * 128) = acc1;
    *(float4*)(base + 2 * 128) = acc2;
    *(float4*)(base + 3 * 128) = acc3;

    // fused el/er: dot this thread's 4 cols against attn vectors, reduce in smem
    float4 al = *(const float4*)(attn_l + jg * 4);
    float4 ar = *(const float4*)(attn_r + jg * 4);
    const int h = jg >> 3;
    atomicAdd(&sEl[rg * 4 + 0][h], acc0.x * al.x + acc0.y * al.y + acc0.z * al.z + acc0.w * al.w);
    atomicAdd(&sEl[rg * 4 + 1][h], acc1.x * al.x + acc1.y * al.y + acc1.z * al.z + acc1.w * al.w);
    atomicAdd(&sEl[rg * 4 + 2][h], acc2.x * al.x + acc2.y * al.y + acc2.z * al.z + acc2.w * al.w);
    atomicAdd(&sEl[rg * 4 + 3][h], acc3.x * al.x + acc3.y * al.y + acc3.z * al.z + acc3.w * al.w);
    atomicAdd(&sEr[rg * 4 + 0][h], acc0.x * ar.x + acc0.y * ar.y + acc0.z * ar.z + acc0.w * ar.w);
    atomicAdd(&sEr[rg * 4 + 1][h], acc1.x * ar.x + acc1.y * ar.y + acc1.z * ar.z + acc1.w * ar.w);
    atomicAdd(&sEr[rg * 4 + 2][h], acc2.x * ar.x + acc2.y * ar.y + acc2.z * ar.z + acc2.w * ar.w);
    atomicAdd(&sEr[rg * 4 + 3][h], acc3.x * ar.x + acc3.y * ar.y + acc3.z * ar.z + acc3.w * ar.w);
    __syncthreads();
    if (t < 128) {
        int row = t >> 2, hh = t & 3;
        ((float*)g_el)[(size_t)(row0 + row) * 4 + hh] = sEl[row][hh];
        ((float*)g_er)[(size_t)(row0 + row) * 4 + hh] = sEr[row][hh];
    }
}

// ---------------- block reductions ------------------------------------------
__device__ __forceinline__ float4 blk_max4(float4 v, float4* sred) {
#pragma unroll
    for (int o = 16; o > 0; o >>= 1) {
        v.x = fmaxf(v.x, __shfl_xor_sync(0xffffffffu, v.x, o));
        v.y = fmaxf(v.y, __shfl_xor_sync(0xffffffffu, v.y, o));
        v.z = fmaxf(v.z, __shfl_xor_sync(0xffffffffu, v.z, o));
        v.w = fmaxf(v.w, __shfl_xor_sync(0xffffffffu, v.w, o));
    }
    int w = threadIdx.x >> 5;
    if ((threadIdx.x & 31) == 0) sred[w] = v;
    __syncthreads();
    if (threadIdx.x == 0) {
        float4 r = sred[0];
        for (int i = 1; i < 4; i++) {
            r.x = fmaxf(r.x, sred[i].x); r.y = fmaxf(r.y, sred[i].y);
            r.z = fmaxf(r.z, sred[i].z); r.w = fmaxf(r.w, sred[i].w);
        }
        sred[0] = r;
    }
    __syncthreads();
    return sred[0];
}

__device__ __forceinline__ float4 blk_sum4(float4 v, float4* sred) {
#pragma unroll
    for (int o = 16; o > 0; o >>= 1) {
        v.x += __shfl_xor_sync(0xffffffffu, v.x, o);
        v.y += __shfl_xor_sync(0xffffffffu, v.y, o);
        v.z += __shfl_xor_sync(0xffffffffu, v.z, o);
        v.w += __shfl_xor_sync(0xffffffffu, v.w, o);
    }
    int w = threadIdx.x >> 5;
    if ((threadIdx.x & 31) == 0) sred[w] = v;
    __syncthreads();
    if (threadIdx.x == 0) {
        float4 r = sred[0];
        for (int i = 1; i < 4; i++) {
            r.x += sred[i].x; r.y += sred[i].y; r.z += sred[i].z; r.w += sred[i].w;
        }
        sred[0] = r;
    }
    __syncthreads();
    return sred[0];
}

// ---------------- 2: fused edge-softmax + gather aggregation ----------------
// grid (Nc, Bc), 128 threads: thread = one output channel; block = one node.
#define CH 128
__global__ void k_agg(float* __restrict__ out) {
    const int n = blockIdx.x, b = blockIdx.y;
    const int tid = threadIdx.x;
    const int h = tid >> 5;
    const int off0 = g_off[n];
    const int deg  = g_off[n + 1] - off0;
    const size_t nb = (size_t)b * Nc + n;

    __shared__ float sw[CH][4];
    __shared__ int   ssrc[CH];
    __shared__ float4 sred[4];

    const float4 er4 = g_er[nb];

    // phase 1: per-head max over incident edges
    float4 m = make_float4(-INFINITY, -INFINITY, -INFINITY, -INFINITY);
    for (int j = tid; j < deg; j += 128) {
        int s = g_csrc[off0 + j];
        float4 el4 = g_el[(size_t)b * Nc + s];
        m.x = fmaxf(m.x, leaky(el4.x + er4.x, GAT_SLOPE));
        m.y = fmaxf(m.y, leaky(el4.y + er4.y, GAT_SLOPE));
        m.z = fmaxf(m.z, leaky(el4.z + er4.z, GAT_SLOPE));
        m.w = fmaxf(m.w, leaky(el4.w + er4.w, GAT_SLOPE));
    }
    m = blk_max4(m, sred);

    // phase 2+3: chunked weights + feature gather (unnormalized; divide once)
    float acc = 0.f;
    float4 dl = make_float4(0, 0, 0, 0);
    for (int base = 0; base < deg; base += CH) {
        int cnt = min(CH, deg - base);
        if (tid < cnt) {
            int s = g_csrc[off0 + base + tid];
            ssrc[tid] = s;
            float4 el4 = g_el[(size_t)b * Nc + s];
            float4 w;
            w.x = expf(leaky(el4.x + er4.x, GAT_SLOPE) - m.x);
            w.y = expf(leaky(el4.y + er4.y, GAT_SLOPE) - m.y);
            w.z = expf(leaky(el4.z + er4.z, GAT_SLOPE) - m.z);
            w.w = expf(leaky(el4.w + er4.w, GAT_SLOPE) - m.w);
            sw[tid][0] = w.x; sw[tid][1] = w.y; sw[tid][2] = w.z; sw[tid][3] = w.w;
            dl.x += w.x; dl.y += w.y; dl.z += w.z; dl.w += w.w;
        }
        __syncthreads();
#pragma unroll 4
        for (int j = 0; j < cnt; j++) {
            acc += sw[j][h] * g_feat[((size_t)b * Nc + ssrc[j]) * 128 + tid];
        }
        __syncthreads();
    }
    float4 den = blk_sum4(dl, sred);
    float d = (h == 0) ? den.x : (h == 1) ? den.y : (h == 2) ? den.z : den.w;
    out[nb * 128 + tid] = acc / fmaxf(d, 1e-9f);
}

// ---------------- 3: BN statistics -------------------------------------------
__global__ void k_bnstats(const float* __restrict__ out) {
    int c = threadIdx.x & 127;
    int r = blockIdx.x * 2 + (threadIdx.x >> 7);
    float s = 0.f, q = 0.f;
    for (; r < BNc; r += gridDim.x * 2) {
        float v = out[(size_t)r * 128 + c];
        s += v; q += v * v;
    }
    atomicAdd(&g_sum[c], s);
    atomicAdd(&g_sq[c], q);
}

__global__ void k_bnfinal(const float* __restrict__ gamma, const float* __restrict__ beta) {
    int c = threadIdx.x;
    float mean = g_sum[c] / (float)BNc;
    float var  = g_sq[c] / (float)BNc - mean * mean;
    float sc = gamma[c] * rsqrtf(var + BN_EPS);
    g_scale[c] = sc;
    g_shift[c] = beta[c] - mean * sc;
}

// ---------------- 4: BN apply + LeakyReLU (in place) -------------------------
__global__ void k_bnapply(float4* out) {
    int i = blockIdx.x * blockDim.x + threadIdx.x;
    int stride = gridDim.x * blockDim.x;
    const int n4 = BNc * HDc / 4;
    for (int p = i; p < n4; p += stride) {
        float4 v = out[p];
        int c = (p & 31) * 4;  // 32 float4 per 128-channel row
        v.x = leaky(v.x * g_scale[c + 0] + g_shift[c + 0], ACT_SLOPE);
        v.y = leaky(v.y * g_scale[c + 1] + g_shift[c + 1], ACT_SLOPE);
        v.z = leaky(v.z * g_scale[c + 2] + g_shift[c + 2], ACT_SLOPE);
        v.w = leaky(v.w * g_scale[c + 3] + g_shift[c + 3], ACT_SLOPE);
        out[p] = v;
    }
}

// ---------------- launch -----------------------------------------------------
extern "C" void kernel_launch(void* const* d_in, const int* in_sizes, int n_in,
                              void* d_out, int out_size) {
    const float* xx     = (const float*)d_in[0];
    const float* W      = (const float*)d_in[1];
    const float* attn_l = (const float*)d_in[2];
    const float* attn_r = (const float*)d_in[3];
    const float* gamma  = (const float*)d_in[4];
    const float* beta   = (const float*)d_in[5];
    const int*   src    = (const int*)d_in[6];
    const int*   dst    = (const int*)d_in[7];
    float* out = (float*)d_out;
    const int E = in_sizes[6];

    k_init<<<64, 256>>>();
    k_hist<<<(E + 511) / 512, 512>>>(dst, E);
    k_scan<<<1, 1024>>>();
    k_scatter<<<(E + 511) / 512, 512>>>(src, dst, E);

    k_gemm<<<BNc / 32, 256>>>(xx, W, attn_l, attn_r);

    dim3 gagg(Nc, Bc);
    k_agg<<<gagg, 128>>>(out);

    k_bnstats<<<1480, 256>>>(out);
    k_bnfinal<<<1, 128>>>(gamma, beta);
    k_bnapply<<<2048, 256>>>((float4*)out);
}

// round 3
// speedup vs baseline: 1.6309x; 1.4071x over previous
#include <cuda_runtime.h>
#include <math.h>

// Problem constants (fixed by the dataset)
#define Bc   4
#define Nc   50000
#define EcMax 800000
#define INc  128
#define Hc   4
#define Dc   32
#define HDc  128
#define BNc  (Bc * Nc)          // 200000 rows
#define GAT_SLOPE 0.2f
#define ACT_SLOPE 0.01f
#define BN_EPS    1e-5f

// ---------------- scratch (device globals; no allocation allowed) ----------
__device__ float    g_feat[(size_t)BNc * HDc];   // 102.4 MB
__device__ float4   g_el[BNc];                   // per-node, per-head (4 heads)
__device__ float4   g_er[BNc];
__device__ int      g_cnt[Nc];                   // in-degree histogram
__device__ int      g_off[Nc + 1];               // CSR offsets
__device__ int      g_wr[Nc];                    // scatter write cursors
__device__ int      g_csrc[EcMax];               // CSR: src node per slot
__device__ float    g_sum[HDc];
__device__ float    g_sq[HDc];
__device__ float    g_scale[HDc];
__device__ float    g_shift[HDc];

__device__ __forceinline__ float leaky(float v, float s) {
    return v >= 0.0f ? v : s * v;
}

__device__ __forceinline__ unsigned f2tf32(float f) {
    unsigned u;
    asm("cvt.rna.tf32.f32 %0, %1;" : "=r"(u) : "f"(f));
    return u;
}

__device__ __forceinline__ void mma_tf32(float* c, const unsigned* a,
                                         unsigned b0, unsigned b1) {
    asm volatile(
        "mma.sync.aligned.m16n8k8.row.col.f32.tf32.tf32.f32 "
        "{%0,%1,%2,%3}, {%4,%5,%6,%7}, {%8,%9}, {%0,%1,%2,%3};"
        : "+f"(c[0]), "+f"(c[1]), "+f"(c[2]), "+f"(c[3])
        : "r"(a[0]), "r"(a[1]), "r"(a[2]), "r"(a[3]), "r"(b0), "r"(b1));
}

// ---------------- 0: zero-init histogram + BN accumulators ------------------
__global__ void k_init() {
    int i = blockIdx.x * blockDim.x + threadIdx.x;
    int stride = gridDim.x * blockDim.x;
    for (int p = i; p < Nc; p += stride) g_cnt[p] = 0;
    if (i < HDc) { g_sum[i] = 0.f; g_sq[i] = 0.f; }
}

// ---------------- CSR build --------------------------------------------------
__global__ void k_hist(const int* __restrict__ dst, int E) {
    int e = blockIdx.x * blockDim.x + threadIdx.x;
    if (e < E) atomicAdd(&g_cnt[dst[e]], 1);
}

// single block, 1024 threads: exclusive scan of g_cnt -> g_off, copy to g_wr
__global__ void k_scan() {
    __shared__ int ssum[1024];
    const int t = threadIdx.x;
    const int per = (Nc + 1023) / 1024;   // 49
    const int base = t * per;
    int s = 0;
    for (int i = 0; i < per; i++) {
        int idx = base + i;
        if (idx < Nc) s += g_cnt[idx];
    }
    ssum[t] = s;
    __syncthreads();
    for (int o = 1; o < 1024; o <<= 1) {
        int v = (t >= o) ? ssum[t - o] : 0;
        __syncthreads();
        ssum[t] += v;
        __syncthreads();
    }
    int run = ssum[t] - s;
    for (int i = 0; i < per; i++) {
        int idx = base + i;
        if (idx < Nc) {
            g_off[idx] = run;
            g_wr[idx]  = run;
            run += g_cnt[idx];
        }
    }
    if (t == 1023) g_off[Nc] = ssum[1023];
}

__global__ void k_scatter(const int* __restrict__ src, const int* __restrict__ dst, int E) {
    int e = blockIdx.x * blockDim.x + threadIdx.x;
    if (e < E) {
        int pos = atomicAdd(&g_wr[dst[e]], 1);
        g_csrc[pos] = src[e];
    }
}

// ---------------- 1: feat = x @ W via tf32 mma, fused el/er epilogue --------
// Block: 256 threads (8 warps, 2m x 4n). Block tile 128 rows x 128 cols.
// Warp tile 64 x 32: 4 m-tiles (16) x 4 n-tiles (8), mma m16n8k8.
__global__ void __launch_bounds__(256, 2)
k_gemm(const float* __restrict__ x, const float* __restrict__ W,
       const float* __restrict__ attn_l, const float* __restrict__ attn_r) {
    __shared__ float xs[128][36];    // [row][k] tf32-rounded, pad 36
    __shared__ float Ws[32][136];    // [k][col] tf32-rounded, pad 136
    __shared__ float sEl[128][4];
    __shared__ float sEr[128][4];

    const int t = threadIdx.x;
    const int lane = t & 31, warp = t >> 5;
    const int wm = warp >> 2, wn = warp & 3;   // warp grid 2 x 4
    const int gid = lane >> 2, tig = lane & 3;
    const int row0 = blockIdx.x * 128;

    // zero el/er accumulators (1024 floats)
    ((float*)sEl)[t] = 0.f; ((float*)sEl)[t + 256] = 0.f;
    ((float*)sEr)[t] = 0.f; ((float*)sEr)[t + 256] = 0.f;

    float acc[4][4][4];
#pragma unroll
    for (int i = 0; i < 4; i++)
#pragma unroll
        for (int j = 0; j < 4; j++)
#pragma unroll
            for (int r = 0; r < 4; r++) acc[i][j][r] = 0.f;

    for (int kc = 0; kc < 128; kc += 32) {
        // stage W tile [32 k][128 c]: 1024 float4, 4 per thread
#pragma unroll
        for (int i = 0; i < 4; i++) {
            int idx = i * 256 + t;
            int k = idx >> 5;           // 32 float4 per k-row
            int c4 = idx & 31;
            float4 v = *(const float4*)(W + (size_t)(kc + k) * 128 + c4 * 4);
            float* dstp = &Ws[k][c4 * 4];
            dstp[0] = __uint_as_float(f2tf32(v.x));
            dstp[1] = __uint_as_float(f2tf32(v.y));
            dstp[2] = __uint_as_float(f2tf32(v.z));
            dstp[3] = __uint_as_float(f2tf32(v.w));
        }
        // stage x tile [128 r][32 k]: 1024 float4, 4 per thread
#pragma unroll
        for (int i = 0; i < 4; i++) {
            int idx = i * 256 + t;
            int r = idx >> 3;           // 8 float4 per row
            int c4 = idx & 7;
            int grow = row0 + r;
            float4 v = make_float4(0.f, 0.f, 0.f, 0.f);
            if (grow < BNc)
                v = *(const float4*)(x + (size_t)grow * 128 + kc + c4 * 4);
            float* dstp = &xs[r][c4 * 4];
            dstp[0] = __uint_as_float(f2tf32(v.x));
            dstp[1] = __uint_as_float(f2tf32(v.y));
            dstp[2] = __uint_as_float(f2tf32(v.z));
            dstp[3] = __uint_as_float(f2tf32(v.w));
        }
        __syncthreads();

#pragma unroll
        for (int ks = 0; ks < 4; ks++) {
            const int k0 = ks * 8;
            unsigned a[4][4];
#pragma unroll
            for (int mt = 0; mt < 4; mt++) {
                int rb = wm * 64 + mt * 16;
                a[mt][0] = __float_as_uint(xs[rb + gid][k0 + tig]);
                a[mt][1] = __float_as_uint(xs[rb + gid + 8][k0 + tig]);
                a[mt][2] = __float_as_uint(xs[rb + gid][k0 + tig + 4]);
                a[mt][3] = __float_as_uint(xs[rb + gid + 8][k0 + tig + 4]);
            }
#pragma unroll
            for (int nt = 0; nt < 4; nt++) {
                int cb = wn * 32 + nt * 8;
                unsigned b0 = __float_as_uint(Ws[k0 + tig][cb + gid]);
                unsigned b1 = __float_as_uint(Ws[k0 + tig + 4][cb + gid]);
#pragma unroll
                for (int mt = 0; mt < 4; mt++)
                    mma_tf32(acc[mt][nt], a[mt], b0, b1);
            }
        }
        __syncthreads();
    }

    // epilogue: store feat + accumulate el/er into smem
#pragma unroll
    for (int mt = 0; mt < 4; mt++) {
        int lr0 = wm * 64 + mt * 16 + gid;   // local rows
        int lr1 = lr0 + 8;
        float el0 = 0.f, el1 = 0.f, er0 = 0.f, er1 = 0.f;
#pragma unroll
        for (int nt = 0; nt < 4; nt++) {
            int c = wn * 32 + nt * 8 + tig * 2;
            float alc0 = attn_l[c], alc1 = attn_l[c + 1];
            float arc0 = attn_r[c], arc1 = attn_r[c + 1];
            float* a4 = acc[mt][nt];
            el0 += a4[0] * alc0 + a4[1] * alc1;
            er0 += a4[0] * arc0 + a4[1] * arc1;
            el1 += a4[2] * alc0 + a4[3] * alc1;
            er1 += a4[2] * arc0 + a4[3] * arc1;
            if (row0 + lr0 < BNc)
                *(float2*)(g_feat + (size_t)(row0 + lr0) * 128 + c) =
                    make_float2(a4[0], a4[1]);
            if (row0 + lr1 < BNc)
                *(float2*)(g_feat + (size_t)(row0 + lr1) * 128 + c) =
                    make_float2(a4[2], a4[3]);
        }
        atomicAdd(&sEl[lr0][wn], el0);
        atomicAdd(&sEl[lr1][wn], el1);
        atomicAdd(&sEr[lr0][wn], er0);
        atomicAdd(&sEr[lr1][wn], er1);
    }
    __syncthreads();
    if (t < 128 && row0 + t < BNc) {
        g_el[row0 + t] = make_float4(sEl[t][0], sEl[t][1], sEl[t][2], sEl[t][3]);
        g_er[row0 + t] = make_float4(sEr[t][0], sEr[t][1], sEr[t][2], sEr[t][3]);
    }
}

// ---------------- 2: fused edge-softmax + gather aggregation ----------------
// grid (Nc, Bc), 128 threads: thread = one output channel; block = one node.
// Softmax without max-subtraction: exp args are small (|e| < ~6) by
// construction, and exp(e)/sum(exp(e)) is mathematically identical.
#define CH 128
__global__ void k_agg(float* __restrict__ out) {
    const int n = blockIdx.x, b = blockIdx.y;
    const int tid = threadIdx.x;
    const int h = tid >> 5;
    const int off0 = g_off[n];
    const int deg  = g_off[n + 1] - off0;
    const size_t nb = (size_t)b * Nc + n;

    if (deg == 0) { out[nb * 128 + tid] = 0.f; return; }

    __shared__ float sw[CH][4];
    __shared__ int   ssrc[CH];

    const float4 er4 = g_er[nb];

    float acc = 0.f, wsum = 0.f;
    for (int base = 0; base < deg; base += CH) {
        int cnt = min(CH, deg - base);
        if (tid < cnt) {
            int s = g_csrc[off0 + base + tid];
            ssrc[tid] = s;
            float4 el4 = g_el[(size_t)b * Nc + s];
            sw[tid][0] = __expf(leaky(el4.x + er4.x, GAT_SLOPE));
            sw[tid][1] = __expf(leaky(el4.y + er4.y, GAT_SLOPE));
            sw[tid][2] = __expf(leaky(el4.z + er4.z, GAT_SLOPE));
            sw[tid][3] = __expf(leaky(el4.w + er4.w, GAT_SLOPE));
        }
        __syncthreads();
#pragma unroll 4
        for (int j = 0; j < cnt; j++) {
            float ww = sw[j][h];
            wsum += ww;
            acc += ww * g_feat[((size_t)b * Nc + ssrc[j]) * 128 + tid];
        }
        __syncthreads();
    }
    out[nb * 128 + tid] = acc / fmaxf(wsum, 1e-9f);
}

// ---------------- 3: BN statistics -------------------------------------------
__global__ void k_bnstats(const float* __restrict__ out) {
    int c = threadIdx.x & 127;
    int r = blockIdx.x * 2 + (threadIdx.x >> 7);
    float s = 0.f, q = 0.f;
    for (; r < BNc; r += gridDim.x * 2) {
        float v = out[(size_t)r * 128 + c];
        s += v; q += v * v;
    }
    atomicAdd(&g_sum[c], s);
    atomicAdd(&g_sq[c], q);
}

__global__ void k_bnfinal(const float* __restrict__ gamma, const float* __restrict__ beta) {
    int c = threadIdx.x;
    float mean = g_sum[c] / (float)BNc;
    float var  = g_sq[c] / (float)BNc - mean * mean;
    float sc = gamma[c] * rsqrtf(var + BN_EPS);
    g_scale[c] = sc;
    g_shift[c] = beta[c] - mean * sc;
}

// ---------------- 4: BN apply + LeakyReLU (in place) -------------------------
__global__ void k_bnapply(float4* out) {
    int i = blockIdx.x * blockDim.x + threadIdx.x;
    int stride = gridDim.x * blockDim.x;
    const int n4 = BNc * HDc / 4;
    for (int p = i; p < n4; p += stride) {
        float4 v = out[p];
        int c = (p & 31) * 4;
        v.x = leaky(v.x * g_scale[c + 0] + g_shift[c + 0], ACT_SLOPE);
        v.y = leaky(v.y * g_scale[c + 1] + g_shift[c + 1], ACT_SLOPE);
        v.z = leaky(v.z * g_scale[c + 2] + g_shift[c + 2], ACT_SLOPE);
        v.w = leaky(v.w * g_scale[c + 3] + g_shift[c + 3], ACT_SLOPE);
        out[p] = v;
    }
}

// ---------------- launch -----------------------------------------------------
extern "C" void kernel_launch(void* const* d_in, const int* in_sizes, int n_in,
                              void* d_out, int out_size) {
    const float* xx     = (const float*)d_in[0];
    const float* W      = (const float*)d_in[1];
    const float* attn_l = (const float*)d_in[2];
    const float* attn_r = (const float*)d_in[3];
    const float* gamma  = (const float*)d_in[4];
    const float* beta   = (const float*)d_in[5];
    const int*   src    = (const int*)d_in[6];
    const int*   dst    = (const int*)d_in[7];
    float* out = (float*)d_out;
    const int E = in_sizes[6];

    k_init<<<64, 256>>>();
    k_hist<<<(E + 511) / 512, 512>>>(dst, E);
    k_scan<<<1, 1024>>>();
    k_scatter<<<(E + 511) / 512, 512>>>(src, dst, E);

    k_gemm<<<(BNc + 127) / 128, 256>>>(xx, W, attn_l, attn_r);

    dim3 gagg(Nc, Bc);
    k_agg<<<gagg, 128>>>(out);

    k_bnstats<<<1480, 256>>>(out);
    k_bnfinal<<<1, 128>>>(gamma, beta);
    k_bnapply<<<2048, 256>>>((float4*)out);
}

// round 4
// speedup vs baseline: 2.0037x; 1.2285x over previous
#include <cuda_runtime.h>
#include <cuda_fp16.h>
#include <math.h>

// Problem constants (fixed by the dataset)
#define Bc   4
#define Nc   50000
#define EcMax 800000
#define INc  128
#define Hc   4
#define Dc   32
#define HDc  128
#define BNc  (Bc * Nc)          // 200000 rows
#define GAT_SLOPE 0.2f
#define ACT_SLOPE 0.01f
#define BN_EPS    1e-5f

// ---------------- scratch (device globals; no allocation allowed) ----------
__device__ __half   g_featH[(size_t)BNc * HDc]; // 51.2 MB (fp16 features)
__device__ float4   g_el[BNc];                  // per-node, per-head (4 heads)
__device__ float4   g_er[BNc];
__device__ int      g_cnt[Nc];                  // in-degree histogram
__device__ int      g_off[Nc + 1];              // CSR offsets
__device__ int      g_wr[Nc];                   // scatter write cursors
__device__ int      g_csrc[EcMax];              // CSR: src node per slot
__device__ float    g_sum[HDc];
__device__ float    g_sq[HDc];
__device__ float    g_scale[HDc];
__device__ float    g_shift[HDc];

__device__ __forceinline__ float leaky(float v, float s) {
    return v >= 0.0f ? v : s * v;
}

__device__ __forceinline__ unsigned f2tf32(float f) {
    unsigned u;
    asm("cvt.rna.tf32.f32 %0, %1;" : "=r"(u) : "f"(f));
    return u;
}

__device__ __forceinline__ void mma_tf32(float* c, const unsigned* a,
                                         unsigned b0, unsigned b1) {
    asm volatile(
        "mma.sync.aligned.m16n8k8.row.col.f32.tf32.tf32.f32 "
        "{%0,%1,%2,%3}, {%4,%5,%6,%7}, {%8,%9}, {%0,%1,%2,%3};"
        : "+f"(c[0]), "+f"(c[1]), "+f"(c[2]), "+f"(c[3])
        : "r"(a[0]), "r"(a[1]), "r"(a[2]), "r"(a[3]), "r"(b0), "r"(b1));
}

// ---------------- 0: zero-init histogram + BN accumulators ------------------
__global__ void k_init() {
    int i = blockIdx.x * blockDim.x + threadIdx.x;
    int stride = gridDim.x * blockDim.x;
    for (int p = i; p < Nc; p += stride) g_cnt[p] = 0;
    if (i < HDc) { g_sum[i] = 0.f; g_sq[i] = 0.f; }
}

// ---------------- CSR build --------------------------------------------------
__global__ void k_hist(const int* __restrict__ dst, int E) {
    int e = blockIdx.x * blockDim.x + threadIdx.x;
    if (e < E) atomicAdd(&g_cnt[dst[e]], 1);
}

// single block, 1024 threads: exclusive scan of g_cnt -> g_off, copy to g_wr
__global__ void k_scan() {
    __shared__ int ssum[1024];
    const int t = threadIdx.x;
    const int per = (Nc + 1023) / 1024;   // 49
    const int base = t * per;
    int s = 0;
    for (int i = 0; i < per; i++) {
        int idx = base + i;
        if (idx < Nc) s += g_cnt[idx];
    }
    ssum[t] = s;
    __syncthreads();
    for (int o = 1; o < 1024; o <<= 1) {
        int v = (t >= o) ? ssum[t - o] : 0;
        __syncthreads();
        ssum[t] += v;
        __syncthreads();
    }
    int run = ssum[t] - s;
    for (int i = 0; i < per; i++) {
        int idx = base + i;
        if (idx < Nc) {
            g_off[idx] = run;
            g_wr[idx]  = run;
            run += g_cnt[idx];
        }
    }
    if (t == 1023) g_off[Nc] = ssum[1023];
}

__global__ void k_scatter(const int* __restrict__ src, const int* __restrict__ dst, int E) {
    int e = blockIdx.x * blockDim.x + threadIdx.x;
    if (e < E) {
        int pos = atomicAdd(&g_wr[dst[e]], 1);
        g_csrc[pos] = src[e];
    }
}

// ---------------- 1: feat = x @ W via tf32 mma, fused el/er epilogue --------
// Block: 256 threads (8 warps, 2m x 4n). Block tile 128 rows x 128 cols.
__global__ void __launch_bounds__(256, 2)
k_gemm(const float* __restrict__ x, const float* __restrict__ W,
       const float* __restrict__ attn_l, const float* __restrict__ attn_r) {
    __shared__ float xs[128][36];    // [row][k] tf32-rounded, pad 36
    __shared__ float Ws[32][136];    // [k][col] tf32-rounded, pad 136
    __shared__ float sEl[128][4];
    __shared__ float sEr[128][4];

    const int t = threadIdx.x;
    const int lane = t & 31, warp = t >> 5;
    const int wm = warp >> 2, wn = warp & 3;   // warp grid 2 x 4
    const int gid = lane >> 2, tig = lane & 3;
    const int row0 = blockIdx.x * 128;

    ((float*)sEl)[t] = 0.f; ((float*)sEl)[t + 256] = 0.f;
    ((float*)sEr)[t] = 0.f; ((float*)sEr)[t + 256] = 0.f;

    float acc[4][4][4];
#pragma unroll
    for (int i = 0; i < 4; i++)
#pragma unroll
        for (int j = 0; j < 4; j++)
#pragma unroll
            for (int r = 0; r < 4; r++) acc[i][j][r] = 0.f;

    for (int kc = 0; kc < 128; kc += 32) {
#pragma unroll
        for (int i = 0; i < 4; i++) {
            int idx = i * 256 + t;
            int k = idx >> 5;
            int c4 = idx & 31;
            float4 v = *(const float4*)(W + (size_t)(kc + k) * 128 + c4 * 4);
            float* dstp = &Ws[k][c4 * 4];
            dstp[0] = __uint_as_float(f2tf32(v.x));
            dstp[1] = __uint_as_float(f2tf32(v.y));
            dstp[2] = __uint_as_float(f2tf32(v.z));
            dstp[3] = __uint_as_float(f2tf32(v.w));
        }
#pragma unroll
        for (int i = 0; i < 4; i++) {
            int idx = i * 256 + t;
            int r = idx >> 3;
            int c4 = idx & 7;
            int grow = row0 + r;
            float4 v = make_float4(0.f, 0.f, 0.f, 0.f);
            if (grow < BNc)
                v = *(const float4*)(x + (size_t)grow * 128 + kc + c4 * 4);
            float* dstp = &xs[r][c4 * 4];
            dstp[0] = __uint_as_float(f2tf32(v.x));
            dstp[1] = __uint_as_float(f2tf32(v.y));
            dstp[2] = __uint_as_float(f2tf32(v.z));
            dstp[3] = __uint_as_float(f2tf32(v.w));
        }
        __syncthreads();

#pragma unroll
        for (int ks = 0; ks < 4; ks++) {
            const int k0 = ks * 8;
            unsigned a[4][4];
#pragma unroll
            for (int mt = 0; mt < 4; mt++) {
                int rb = wm * 64 + mt * 16;
                a[mt][0] = __float_as_uint(xs[rb + gid][k0 + tig]);
                a[mt][1] = __float_as_uint(xs[rb + gid + 8][k0 + tig]);
                a[mt][2] = __float_as_uint(xs[rb + gid][k0 + tig + 4]);
                a[mt][3] = __float_as_uint(xs[rb + gid + 8][k0 + tig + 4]);
            }
#pragma unroll
            for (int nt = 0; nt < 4; nt++) {
                int cb = wn * 32 + nt * 8;
                unsigned b0 = __float_as_uint(Ws[k0 + tig][cb + gid]);
                unsigned b1 = __float_as_uint(Ws[k0 + tig + 4][cb + gid]);
#pragma unroll
                for (int mt = 0; mt < 4; mt++)
                    mma_tf32(acc[mt][nt], a[mt], b0, b1);
            }
        }
        __syncthreads();
    }

    // epilogue: store feat (fp16) + accumulate el/er into smem
#pragma unroll
    for (int mt = 0; mt < 4; mt++) {
        int lr0 = wm * 64 + mt * 16 + gid;
        int lr1 = lr0 + 8;
        float el0 = 0.f, el1 = 0.f, er0 = 0.f, er1 = 0.f;
#pragma unroll
        for (int nt = 0; nt < 4; nt++) {
            int c = wn * 32 + nt * 8 + tig * 2;
            float alc0 = attn_l[c], alc1 = attn_l[c + 1];
            float arc0 = attn_r[c], arc1 = attn_r[c + 1];
            float* a4 = acc[mt][nt];
            el0 += a4[0] * alc0 + a4[1] * alc1;
            er0 += a4[0] * arc0 + a4[1] * arc1;
            el1 += a4[2] * alc0 + a4[3] * alc1;
            er1 += a4[2] * arc0 + a4[3] * arc1;
            if (row0 + lr0 < BNc)
                *(__half2*)(g_featH + (size_t)(row0 + lr0) * 128 + c) =
                    __floats2half2_rn(a4[0], a4[1]);
            if (row0 + lr1 < BNc)
                *(__half2*)(g_featH + (size_t)(row0 + lr1) * 128 + c) =
                    __floats2half2_rn(a4[2], a4[3]);
        }
        atomicAdd(&sEl[lr0][wn], el0);
        atomicAdd(&sEl[lr1][wn], el1);
        atomicAdd(&sEr[lr0][wn], er0);
        atomicAdd(&sEr[lr1][wn], er1);
    }
    __syncthreads();
    if (t < 128 && row0 + t < BNc) {
        g_el[row0 + t] = make_float4(sEl[t][0], sEl[t][1], sEl[t][2], sEl[t][3]);
        g_er[row0 + t] = make_float4(sEr[t][0], sEr[t][1], sEr[t][2], sEr[t][3]);
    }
}

// ---------------- 2: fused edge-softmax + gather aggregation ----------------
// grid (Nc, Bc), 64 threads: thread = one half2 channel pair; block = node.
// Softmax without max-subtraction: exp(e)/sum(exp(e)) identical; |e| small.
#define CH 64
__global__ void k_agg(float* __restrict__ out) {
    const int n = blockIdx.x, b = blockIdx.y;
    const int tid = threadIdx.x;          // 0..63, channels 2t, 2t+1
    const int h = tid >> 4;               // head = (2t)/32
    const int off0 = g_off[n];
    const int deg  = g_off[n + 1] - off0;
    const size_t nb = (size_t)b * Nc + n;

    if (deg == 0) {
        *(float2*)(out + nb * 128 + tid * 2) = make_float2(0.f, 0.f);
        return;
    }

    __shared__ float sw[CH][4];
    __shared__ int   ssrc[CH];

    const float4 er4 = g_er[nb];

    float ax = 0.f, ay = 0.f, wsum = 0.f;
    for (int base = 0; base < deg; base += CH) {
        int cnt = min(CH, deg - base);
        if (tid < cnt) {
            int s = g_csrc[off0 + base + tid];
            ssrc[tid] = s;
            float4 el4 = g_el[(size_t)b * Nc + s];
            sw[tid][0] = __expf(leaky(el4.x + er4.x, GAT_SLOPE));
            sw[tid][1] = __expf(leaky(el4.y + er4.y, GAT_SLOPE));
            sw[tid][2] = __expf(leaky(el4.z + er4.z, GAT_SLOPE));
            sw[tid][3] = __expf(leaky(el4.w + er4.w, GAT_SLOPE));
        }
        __syncthreads();
#pragma unroll 4
        for (int j = 0; j < cnt; j++) {
            float ww = sw[j][h];
            wsum += ww;
            __half2 f = *(const __half2*)(g_featH +
                         ((size_t)b * Nc + ssrc[j]) * 128 + tid * 2);
            float2 ff = __half22float2(f);
            ax += ww * ff.x;
            ay += ww * ff.y;
        }
        __syncthreads();
    }
    float inv = 1.f / fmaxf(wsum, 1e-9f);
    *(float2*)(out + nb * 128 + tid * 2) = make_float2(ax * inv, ay * inv);
}

// ---------------- 3: BN statistics -------------------------------------------
__global__ void k_bnstats(const float* __restrict__ out) {
    int c = threadIdx.x & 127;
    int r = blockIdx.x * 2 + (threadIdx.x >> 7);
    float s = 0.f, q = 0.f;
    for (; r < BNc; r += gridDim.x * 2) {
        float v = out[(size_t)r * 128 + c];
        s += v; q += v * v;
    }
    atomicAdd(&g_sum[c], s);
    atomicAdd(&g_sq[c], q);
}

__global__ void k_bnfinal(const float* __restrict__ gamma, const float* __restrict__ beta) {
    int c = threadIdx.x;
    float mean = g_sum[c] / (float)BNc;
    float var  = g_sq[c] / (float)BNc - mean * mean;
    float sc = gamma[c] * rsqrtf(var + BN_EPS);
    g_scale[c] = sc;
    g_shift[c] = beta[c] - mean * sc;
}

// ---------------- 4: BN apply + LeakyReLU (in place) -------------------------
__global__ void k_bnapply(float4* out) {
    int i = blockIdx.x * blockDim.x + threadIdx.x;
    int stride = gridDim.x * blockDim.x;
    const int n4 = BNc * HDc / 4;
    for (int p = i; p < n4; p += stride) {
        float4 v = out[p];
        int c = (p & 31) * 4;
        v.x = leaky(v.x * g_scale[c + 0] + g_shift[c + 0], ACT_SLOPE);
        v.y = leaky(v.y * g_scale[c + 1] + g_shift[c + 1], ACT_SLOPE);
        v.z = leaky(v.z * g_scale[c + 2] + g_shift[c + 2], ACT_SLOPE);
        v.w = leaky(v.w * g_scale[c + 3] + g_shift[c + 3], ACT_SLOPE);
        out[p] = v;
    }
}

// ---------------- launch -----------------------------------------------------
extern "C" void kernel_launch(void* const* d_in, const int* in_sizes, int n_in,
                              void* d_out, int out_size) {
    const float* xx     = (const float*)d_in[0];
    const float* W      = (const float*)d_in[1];
    const float* attn_l = (const float*)d_in[2];
    const float* attn_r = (const float*)d_in[3];
    const float* gamma  = (const float*)d_in[4];
    const float* beta   = (const float*)d_in[5];
    const int*   src    = (const int*)d_in[6];
    const int*   dst    = (const int*)d_in[7];
    float* out = (float*)d_out;
    const int E = in_sizes[6];

    // side stream + events for capturing the CSR build in parallel with GEMM
    static cudaStream_t s2 = nullptr;
    static cudaEvent_t evFork = nullptr, evJoin = nullptr;
    if (s2 == nullptr) {
        cudaStreamCreateWithFlags(&s2, cudaStreamNonBlocking);
        cudaEventCreateWithFlags(&evFork, cudaEventDisableTiming);
        cudaEventCreateWithFlags(&evJoin, cudaEventDisableTiming);
    }

    // fork: CSR build on s2, GEMM on main stream (independent work)
    cudaEventRecord(evFork, 0);
    cudaStreamWaitEvent(s2, evFork, 0);

    k_init<<<64, 256, 0, s2>>>();
    k_hist<<<(E + 511) / 512, 512, 0, s2>>>(dst, E);
    k_scan<<<1, 1024, 0, s2>>>();
    k_scatter<<<(E + 511) / 512, 512, 0, s2>>>(src, dst, E);
    cudaEventRecord(evJoin, s2);

    k_gemm<<<(BNc + 127) / 128, 256>>>(xx, W, attn_l, attn_r);

    // join
    cudaStreamWaitEvent(0, evJoin, 0);

    dim3 gagg(Nc, Bc);
    k_agg<<<gagg, 64>>>(out);

    k_bnstats<<<1480, 256>>>(out);
    k_bnfinal<<<1, 128>>>(gamma, beta);
    k_bnapply<<<2048, 256>>>((float4*)out);
}

// round 5
// speedup vs baseline: 2.0106x; 1.0035x over previous
#include <cuda_runtime.h>
#include <cuda_fp16.h>
#include <math.h>

// Problem constants (fixed by the dataset)
#define Bc   4
#define Nc   50000
#define EcMax 800000
#define INc  128
#define Hc   4
#define Dc   32
#define HDc  128
#define BNc  (Bc * Nc)          // 200000 rows
#define GAT_SLOPE 0.2f
#define ACT_SLOPE 0.01f
#define BN_EPS    1e-5f

// ---------------- scratch (device globals; no allocation allowed) ----------
__device__ __half   g_featH[(size_t)BNc * HDc]; // 51.2 MB (fp16 features)
__device__ float4   g_el[BNc];                  // per-node, per-head (4 heads)
__device__ float4   g_er[BNc];
__device__ int      g_cnt[Nc];                  // in-degree histogram
__device__ int      g_off[Nc + 1];              // CSR offsets
__device__ int      g_wr[Nc];                   // scatter write cursors
__device__ int      g_csrc[EcMax];              // CSR: src node per slot
__device__ float    g_sum[HDc];
__device__ float    g_sq[HDc];
__device__ float    g_scale[HDc];
__device__ float    g_shift[HDc];

__device__ __forceinline__ float leaky(float v, float s) {
    return v >= 0.0f ? v : s * v;
}

__device__ __forceinline__ unsigned f2tf32(float f) {
    unsigned u;
    asm("cvt.rna.tf32.f32 %0, %1;" : "=r"(u) : "f"(f));
    return u;
}

__device__ __forceinline__ void mma_tf32(float* c, const unsigned* a,
                                         unsigned b0, unsigned b1) {
    asm volatile(
        "mma.sync.aligned.m16n8k8.row.col.f32.tf32.tf32.f32 "
        "{%0,%1,%2,%3}, {%4,%5,%6,%7}, {%8,%9}, {%0,%1,%2,%3};"
        : "+f"(c[0]), "+f"(c[1]), "+f"(c[2]), "+f"(c[3])
        : "r"(a[0]), "r"(a[1]), "r"(a[2]), "r"(a[3]), "r"(b0), "r"(b1));
}

// ---------------- 0: zero-init histogram + BN accumulators ------------------
__global__ void k_init() {
    int i = blockIdx.x * blockDim.x + threadIdx.x;
    int stride = gridDim.x * blockDim.x;
    for (int p = i; p < Nc; p += stride) g_cnt[p] = 0;
    if (i < HDc) { g_sum[i] = 0.f; g_sq[i] = 0.f; }
}

// ---------------- CSR build --------------------------------------------------
__global__ void k_hist(const int* __restrict__ dst, int E) {
    int e = blockIdx.x * blockDim.x + threadIdx.x;
    if (e < E) atomicAdd(&g_cnt[dst[e]], 1);
}

__global__ void k_scan() {
    __shared__ int ssum[1024];
    const int t = threadIdx.x;
    const int per = (Nc + 1023) / 1024;   // 49
    const int base = t * per;
    int s = 0;
    for (int i = 0; i < per; i++) {
        int idx = base + i;
        if (idx < Nc) s += g_cnt[idx];
    }
    ssum[t] = s;
    __syncthreads();
    for (int o = 1; o < 1024; o <<= 1) {
        int v = (t >= o) ? ssum[t - o] : 0;
        __syncthreads();
        ssum[t] += v;
        __syncthreads();
    }
    int run = ssum[t] - s;
    for (int i = 0; i < per; i++) {
        int idx = base + i;
        if (idx < Nc) {
            g_off[idx] = run;
            g_wr[idx]  = run;
            run += g_cnt[idx];
        }
    }
    if (t == 1023) g_off[Nc] = ssum[1023];
}

__global__ void k_scatter(const int* __restrict__ src, const int* __restrict__ dst, int E) {
    int e = blockIdx.x * blockDim.x + threadIdx.x;
    if (e < E) {
        int pos = atomicAdd(&g_wr[dst[e]], 1);
        g_csrc[pos] = src[e];
    }
}

// ---------------- 1: feat = x @ W via tf32 mma, single-stage full-K tiles ---
// Block: 256 threads (8 warps, 2m x 4n). Block tile 128 rows x 128 cols.
#define XS_LD 132
#define WS_LD 136
#define SMEM_GEMM ((128 * XS_LD + 128 * WS_LD + 1024) * 4)
__global__ void __launch_bounds__(256, 1)
k_gemm(const float* __restrict__ x, const float* __restrict__ W,
       const float* __restrict__ attn_l, const float* __restrict__ attn_r) {
    extern __shared__ float smem[];
    float* xs  = smem;                       // [128][XS_LD]
    float* Ws  = smem + 128 * XS_LD;         // [128][WS_LD]
    float* sEl = Ws + 128 * WS_LD;           // [128][4]
    float* sEr = sEl + 512;                  // [128][4]

    const int t = threadIdx.x;
    const int lane = t & 31, warp = t >> 5;
    const int wm = warp >> 2, wn = warp & 3;   // warp grid 2 x 4
    const int gid = lane >> 2, tig = lane & 3;
    const int row0 = blockIdx.x * 128;

    sEl[t] = 0.f; sEl[t + 256] = 0.f;
    sEr[t] = 0.f; sEr[t + 256] = 0.f;

    // stage full W [128k][128c] and x [128r][128k], tf32-rounded
#pragma unroll
    for (int i = 0; i < 16; i++) {
        int idx = i * 256 + t;
        int k = idx >> 5, c4 = idx & 31;
        float4 v = *(const float4*)(W + (size_t)k * 128 + c4 * 4);
        float* dstp = &Ws[k * WS_LD + c4 * 4];
        dstp[0] = __uint_as_float(f2tf32(v.x));
        dstp[1] = __uint_as_float(f2tf32(v.y));
        dstp[2] = __uint_as_float(f2tf32(v.z));
        dstp[3] = __uint_as_float(f2tf32(v.w));
    }
#pragma unroll
    for (int i = 0; i < 16; i++) {
        int idx = i * 256 + t;
        int r = idx >> 5, c4 = idx & 31;
        int grow = row0 + r;
        float4 v = make_float4(0.f, 0.f, 0.f, 0.f);
        if (grow < BNc)
            v = *(const float4*)(x + (size_t)grow * 128 + c4 * 4);
        float* dstp = &xs[r * XS_LD + c4 * 4];
        dstp[0] = __uint_as_float(f2tf32(v.x));
        dstp[1] = __uint_as_float(f2tf32(v.y));
        dstp[2] = __uint_as_float(f2tf32(v.z));
        dstp[3] = __uint_as_float(f2tf32(v.w));
    }
    __syncthreads();

    float acc[4][4][4];
#pragma unroll
    for (int i = 0; i < 4; i++)
#pragma unroll
        for (int j = 0; j < 4; j++)
#pragma unroll
            for (int r = 0; r < 4; r++) acc[i][j][r] = 0.f;

#pragma unroll
    for (int ks = 0; ks < 16; ks++) {
        const int k0 = ks * 8;
        unsigned a[4][4];
#pragma unroll
        for (int mt = 0; mt < 4; mt++) {
            int rb = wm * 64 + mt * 16;
            a[mt][0] = __float_as_uint(xs[(rb + gid) * XS_LD + k0 + tig]);
            a[mt][1] = __float_as_uint(xs[(rb + gid + 8) * XS_LD + k0 + tig]);
            a[mt][2] = __float_as_uint(xs[(rb + gid) * XS_LD + k0 + tig + 4]);
            a[mt][3] = __float_as_uint(xs[(rb + gid + 8) * XS_LD + k0 + tig + 4]);
        }
#pragma unroll
        for (int nt = 0; nt < 4; nt++) {
            int cb = wn * 32 + nt * 8;
            unsigned b0 = __float_as_uint(Ws[(k0 + tig) * WS_LD + cb + gid]);
            unsigned b1 = __float_as_uint(Ws[(k0 + tig + 4) * WS_LD + cb + gid]);
#pragma unroll
            for (int mt = 0; mt < 4; mt++)
                mma_tf32(acc[mt][nt], a[mt], b0, b1);
        }
    }

    // epilogue: store feat (fp16) + accumulate el/er into smem
#pragma unroll
    for (int mt = 0; mt < 4; mt++) {
        int lr0 = wm * 64 + mt * 16 + gid;
        int lr1 = lr0 + 8;
        float el0 = 0.f, el1 = 0.f, er0 = 0.f, er1 = 0.f;
#pragma unroll
        for (int nt = 0; nt < 4; nt++) {
            int c = wn * 32 + nt * 8 + tig * 2;
            float alc0 = attn_l[c], alc1 = attn_l[c + 1];
            float arc0 = attn_r[c], arc1 = attn_r[c + 1];
            float* a4 = acc[mt][nt];
            el0 += a4[0] * alc0 + a4[1] * alc1;
            er0 += a4[0] * arc0 + a4[1] * arc1;
            el1 += a4[2] * alc0 + a4[3] * alc1;
            er1 += a4[2] * arc0 + a4[3] * arc1;
            if (row0 + lr0 < BNc)
                *(__half2*)(g_featH + (size_t)(row0 + lr0) * 128 + c) =
                    __floats2half2_rn(a4[0], a4[1]);
            if (row0 + lr1 < BNc)
                *(__half2*)(g_featH + (size_t)(row0 + lr1) * 128 + c) =
                    __floats2half2_rn(a4[2], a4[3]);
        }
        atomicAdd(&sEl[lr0 * 4 + wn], el0);
        atomicAdd(&sEl[lr1 * 4 + wn], el1);
        atomicAdd(&sEr[lr0 * 4 + wn], er0);
        atomicAdd(&sEr[lr1 * 4 + wn], er1);
    }
    __syncthreads();
    if (t < 128 && row0 + t < BNc) {
        g_el[row0 + t] = make_float4(sEl[t * 4], sEl[t * 4 + 1], sEl[t * 4 + 2], sEl[t * 4 + 3]);
        g_er[row0 + t] = make_float4(sEr[t * 4], sEr[t * 4 + 1], sEr[t * 4 + 2], sEr[t * 4 + 3]);
    }
}

// ---------------- 2: fused edge-softmax + gather aggregation ----------------
// grid (Nc), 128 threads: block = one node, ALL 4 batches.
// thread: cp = tid&63 -> channels 2cp,2cp+1 ; bp = tid>>6 -> batches 2bp,2bp+1
// Softmax without max-subtraction: exp(e)/sum(exp(e)) identical; |e| small.
#define CHb 32
__global__ void __launch_bounds__(128, 8) k_agg(float* __restrict__ out) {
    const int n = blockIdx.x;
    const int tid = threadIdx.x;
    const int cp = tid & 63;
    const int bp = tid >> 6;
    const int h = cp >> 4;
    const int off0 = g_off[n];
    const int deg  = g_off[n + 1] - off0;
    const int b0 = 2 * bp, b1 = 2 * bp + 1;

    if (deg == 0) {
        *(float2*)(out + ((size_t)b0 * Nc + n) * 128 + cp * 2) = make_float2(0.f, 0.f);
        *(float2*)(out + ((size_t)b1 * Nc + n) * 128 + cp * 2) = make_float2(0.f, 0.f);
        return;
    }

    __shared__ int   ssrc[CHb];
    __shared__ float sw[CHb][4][4];   // [edge][batch][head]
    __shared__ float4 ser[4];

    if (tid < 4) ser[tid] = g_er[(size_t)tid * Nc + n];
    __syncthreads();

    float ax0 = 0.f, ay0 = 0.f, ax1 = 0.f, ay1 = 0.f;
    float ws0 = 0.f, ws1 = 0.f;

    for (int base = 0; base < deg; base += CHb) {
        int cnt = min(CHb, deg - base);
        {
            int e = tid & 31, b = tid >> 5;   // 32 edges x 4 batches
            if (e < cnt) {
                int s = g_csrc[off0 + base + e];
                if (b == 0) ssrc[e] = s;
                float4 el4 = g_el[(size_t)b * Nc + s];
                float4 er4 = ser[b];
                sw[e][b][0] = __expf(leaky(el4.x + er4.x, GAT_SLOPE));
                sw[e][b][1] = __expf(leaky(el4.y + er4.y, GAT_SLOPE));
                sw[e][b][2] = __expf(leaky(el4.z + er4.z, GAT_SLOPE));
                sw[e][b][3] = __expf(leaky(el4.w + er4.w, GAT_SLOPE));
            }
        }
        __syncthreads();
#pragma unroll 4
        for (int j = 0; j < cnt; j++) {
            int s = ssrc[j];
            float w0 = sw[j][b0][h];
            float w1 = sw[j][b1][h];
            ws0 += w0; ws1 += w1;
            __half2 f0 = *(const __half2*)(g_featH + ((size_t)b0 * Nc + s) * 128 + cp * 2);
            __half2 f1 = *(const __half2*)(g_featH + ((size_t)b1 * Nc + s) * 128 + cp * 2);
            float2 ff0 = __half22float2(f0);
            float2 ff1 = __half22float2(f1);
            ax0 += w0 * ff0.x; ay0 += w0 * ff0.y;
            ax1 += w1 * ff1.x; ay1 += w1 * ff1.y;
        }
        __syncthreads();
    }
    float inv0 = 1.f / fmaxf(ws0, 1e-9f);
    float inv1 = 1.f / fmaxf(ws1, 1e-9f);
    *(float2*)(out + ((size_t)b0 * Nc + n) * 128 + cp * 2) = make_float2(ax0 * inv0, ay0 * inv0);
    *(float2*)(out + ((size_t)b1 * Nc + n) * 128 + cp * 2) = make_float2(ax1 * inv1, ay1 * inv1);
}

// ---------------- 3: BN statistics -------------------------------------------
__global__ void k_bnstats(const float* __restrict__ out) {
    int c = threadIdx.x & 127;
    int r = blockIdx.x * 2 + (threadIdx.x >> 7);
    float s = 0.f, q = 0.f;
    for (; r < BNc; r += gridDim.x * 2) {
        float v = out[(size_t)r * 128 + c];
        s += v; q += v * v;
    }
    atomicAdd(&g_sum[c], s);
    atomicAdd(&g_sq[c], q);
}

__global__ void k_bnfinal(const float* __restrict__ gamma, const float* __restrict__ beta) {
    int c = threadIdx.x;
    float mean = g_sum[c] / (float)BNc;
    float var  = g_sq[c] / (float)BNc - mean * mean;
    float sc = gamma[c] * rsqrtf(var + BN_EPS);
    g_scale[c] = sc;
    g_shift[c] = beta[c] - mean * sc;
}

// ---------------- 4: BN apply + LeakyReLU (in place) -------------------------
__global__ void k_bnapply(float4* out) {
    int i = blockIdx.x * blockDim.x + threadIdx.x;
    int stride = gridDim.x * blockDim.x;
    const int n4 = BNc * HDc / 4;
    for (int p = i; p < n4; p += stride) {
        float4 v = out[p];
        int c = (p & 31) * 4;
        v.x = leaky(v.x * g_scale[c + 0] + g_shift[c + 0], ACT_SLOPE);
        v.y = leaky(v.y * g_scale[c + 1] + g_shift[c + 1], ACT_SLOPE);
        v.z = leaky(v.z * g_scale[c + 2] + g_shift[c + 2], ACT_SLOPE);
        v.w = leaky(v.w * g_scale[c + 3] + g_shift[c + 3], ACT_SLOPE);
        out[p] = v;
    }
}

// ---------------- launch -----------------------------------------------------
extern "C" void kernel_launch(void* const* d_in, const int* in_sizes, int n_in,
                              void* d_out, int out_size) {
    const float* xx     = (const float*)d_in[0];
    const float* W      = (const float*)d_in[1];
    const float* attn_l = (const float*)d_in[2];
    const float* attn_r = (const float*)d_in[3];
    const float* gamma  = (const float*)d_in[4];
    const float* beta   = (const float*)d_in[5];
    const int*   src    = (const int*)d_in[6];
    const int*   dst    = (const int*)d_in[7];
    float* out = (float*)d_out;
    const int E = in_sizes[6];

    static cudaStream_t s2 = nullptr;
    static cudaEvent_t evFork = nullptr, evJoin = nullptr;
    if (s2 == nullptr) {
        cudaStreamCreateWithFlags(&s2, cudaStreamNonBlocking);
        cudaEventCreateWithFlags(&evFork, cudaEventDisableTiming);
        cudaEventCreateWithFlags(&evJoin, cudaEventDisableTiming);
        cudaFuncSetAttribute(k_gemm, cudaFuncAttributeMaxDynamicSharedMemorySize,
                             SMEM_GEMM);
    }

    // fork: CSR build on s2, GEMM on main stream (independent work)
    cudaEventRecord(evFork, 0);
    cudaStreamWaitEvent(s2, evFork, 0);

    k_init<<<64, 256, 0, s2>>>();
    k_hist<<<(E + 511) / 512, 512, 0, s2>>>(dst, E);
    k_scan<<<1, 1024, 0, s2>>>();
    k_scatter<<<(E + 511) / 512, 512, 0, s2>>>(src, dst, E);
    cudaEventRecord(evJoin, s2);

    k_gemm<<<(BNc + 127) / 128, 256, SMEM_GEMM>>>(xx, W, attn_l, attn_r);

    cudaStreamWaitEvent(0, evJoin, 0);

    k_agg<<<Nc, 128>>>(out);

    k_bnstats<<<1480, 256>>>(out);
    k_bnfinal<<<1, 128>>>(gamma, beta);
    k_bnapply<<<2048, 256>>>((float4*)out);
}